// round 6
// baseline (speedup 1.0000x reference)
#include <cuda_runtime.h>
#include <math.h>
#include <stdint.h>

// Problem dims
constexpr int BATCH = 2;
constexpr int SEQ   = 2048;
constexpr int HID   = 4096;
constexpr int NHEADS = 32;
constexpr int NKVH   = 8;
constexpr int HDIM   = 128;
constexpr int GRP    = NHEADS / NKVH;          // 4
constexpr int MROWS  = BATCH * SEQ;            // 4096
constexpr int NQCOLS = NHEADS * HDIM;          // 4096
constexpr int NKVCOLS = NKVH * HDIM;           // 1024

// Scratch (device globals; no runtime allocation allowed)
__device__ float g_Q[(size_t)MROWS * NQCOLS];
__device__ float g_K[(size_t)MROWS * NKVCOLS];
__device__ float g_V[(size_t)MROWS * NKVCOLS];
__device__ float g_AO[(size_t)MROWS * NQCOLS];

// ---------------------------------------------------------------------------
// mma helpers (legacy mma.sync path — tcgen05 PTX is rejected by the harness's
// compute_103 virtual-arch build, per R5 failure)
// ---------------------------------------------------------------------------
__device__ __forceinline__ uint32_t f2tf32(float x) {
    uint32_t u;
    asm("cvt.rna.tf32.f32 %0, %1;" : "=r"(u) : "f"(x));
    return u;
}

__device__ __forceinline__ void split_tf32(float x, uint32_t& hi, uint32_t& lo) {
    hi = f2tf32(x);
    lo = f2tf32(x - __uint_as_float(hi));
}

__device__ __forceinline__ uint2 split2_tf32(float x) {
    uint2 r;
    r.x = f2tf32(x);
    r.y = f2tf32(x - __uint_as_float(r.x));
    return r;
}

__device__ __forceinline__ void mma_tf32(float c[4], const uint32_t a[4], const uint32_t b[2]) {
    asm volatile(
        "mma.sync.aligned.m16n8k8.row.col.f32.tf32.tf32.f32 "
        "{%0,%1,%2,%3}, {%4,%5,%6,%7}, {%8,%9}, {%0,%1,%2,%3};\n"
        : "+f"(c[0]), "+f"(c[1]), "+f"(c[2]), "+f"(c[3])
        : "r"(a[0]), "r"(a[1]), "r"(a[2]), "r"(a[3]), "r"(b[0]), "r"(b[1]));
}

// ---------------------------------------------------------------------------
// TF32 tensor-core GEMM NT: C[M,N] = A[M,K] * B[N,K]^T (row-major, fp32 I/O).
// Block 128x128x32, 8 warps of 32x64. Smem stride 36 => conflict-free LDS.
// (R4-proven version.)
// ---------------------------------------------------------------------------
constexpr int TBM = 128, TBN = 128, TBK = 32, TSST = 36;

__global__ __launch_bounds__(256, 1)
void tgemm_nt_tf32(const float* __restrict__ A, const float* __restrict__ Bm,
                   float* __restrict__ C, int Ndim, int Kdim)
{
    __shared__ uint32_t As[TBM * TSST];
    __shared__ uint32_t Bs[TBN * TSST];

    const int tid  = threadIdx.x;
    const int lane = tid & 31;
    const int wid  = tid >> 5;
    const int wm   = (wid >> 1) * 32;
    const int wn   = (wid & 1) * 64;
    const int lr   = lane >> 2;
    const int lc   = lane & 3;
    const int bm0  = blockIdx.y * TBM;
    const int bn0  = blockIdx.x * TBN;

    const int grow = tid >> 3;
    const int gkc  = (tid & 7) * 4;

    const float* Ap = A  + (size_t)(bm0 + grow) * Kdim + gkc;
    const float* Bp = Bm + (size_t)(bn0 + grow) * Kdim + gkc;

    float4 pa[4], pb[4];
#pragma unroll
    for (int i = 0; i < 4; i++) {
        pa[i] = *reinterpret_cast<const float4*>(Ap + (size_t)i * 32 * Kdim);
        pb[i] = *reinterpret_cast<const float4*>(Bp + (size_t)i * 32 * Kdim);
    }

    float cfr[2][8][4];
#pragma unroll
    for (int mt = 0; mt < 2; mt++)
#pragma unroll
        for (int nt = 0; nt < 8; nt++)
#pragma unroll
            for (int q = 0; q < 4; q++) cfr[mt][nt][q] = 0.f;

    int k0 = 0;
    for (;;) {
#pragma unroll
        for (int i = 0; i < 4; i++) {
            uint32_t* d = &As[(grow + i * 32) * TSST + gkc];
            d[0] = f2tf32(pa[i].x); d[1] = f2tf32(pa[i].y);
            d[2] = f2tf32(pa[i].z); d[3] = f2tf32(pa[i].w);
            uint32_t* e = &Bs[(grow + i * 32) * TSST + gkc];
            e[0] = f2tf32(pb[i].x); e[1] = f2tf32(pb[i].y);
            e[2] = f2tf32(pb[i].z); e[3] = f2tf32(pb[i].w);
        }
        __syncthreads();

        k0 += TBK;
        const bool more = (k0 < Kdim);
        if (more) {
#pragma unroll
            for (int i = 0; i < 4; i++) {
                pa[i] = *reinterpret_cast<const float4*>(Ap + k0 + (size_t)i * 32 * Kdim);
                pb[i] = *reinterpret_cast<const float4*>(Bp + k0 + (size_t)i * 32 * Kdim);
            }
        }

#pragma unroll
        for (int ks = 0; ks < 4; ks++) {
            uint32_t af[2][4], bf[8][2];
#pragma unroll
            for (int mt = 0; mt < 2; mt++) {
                const uint32_t* p = &As[(wm + mt * 16 + lr) * TSST + ks * 8 + lc];
                af[mt][0] = p[0];
                af[mt][1] = p[8 * TSST];
                af[mt][2] = p[4];
                af[mt][3] = p[8 * TSST + 4];
            }
#pragma unroll
            for (int nt = 0; nt < 8; nt++) {
                const uint32_t* p = &Bs[(wn + nt * 8 + lr) * TSST + ks * 8 + lc];
                bf[nt][0] = p[0];
                bf[nt][1] = p[4];
            }
#pragma unroll
            for (int mt = 0; mt < 2; mt++)
#pragma unroll
                for (int nt = 0; nt < 8; nt++)
                    mma_tf32(cfr[mt][nt], af[mt], bf[nt]);
        }

        if (!more) break;
        __syncthreads();
    }

#pragma unroll
    for (int mt = 0; mt < 2; mt++)
#pragma unroll
        for (int nt = 0; nt < 8; nt++) {
            const int row = bm0 + wm + mt * 16 + lr;
            const int col = bn0 + wn + nt * 8 + lc * 2;
            *reinterpret_cast<float2*>(&C[(size_t)row * Ndim + col]) =
                make_float2(cfr[mt][nt][0], cfr[mt][nt][1]);
            *reinterpret_cast<float2*>(&C[(size_t)(row + 8) * Ndim + col]) =
                make_float2(cfr[mt][nt][2], cfr[mt][nt][3]);
        }
}

// ---------------------------------------------------------------------------
// RoPE (in place). position_ids is arange(S) broadcast -> t = row % SEQ.
// ---------------------------------------------------------------------------
__global__ void rope_kernel(float* __restrict__ X, int ncols,
                            const float* __restrict__ cosv, const float* __restrict__ sinv)
{
    const int pairs = ncols >> 1;
    const int idx = blockIdx.x * blockDim.x + threadIdx.x;
    const int total = MROWS * pairs;
    if (idx >= total) return;
    const int m = idx / pairs;
    const int p = idx - m * pairs;
    const int head = p >> 6;
    const int i = p & 63;
    const int t = m & (SEQ - 1);
    const float c = cosv[t * 64 + i];
    const float s = sinv[t * 64 + i];
    float2* xp = reinterpret_cast<float2*>(X + (size_t)m * ncols + head * HDIM + 2 * i);
    float2 v = *xp;
    *xp = make_float2(v.x * c - v.y * s, v.x * s + v.y * c);
}

// ---------------------------------------------------------------------------
// Flash attention v2: Q/K/V pre-split into (hi,lo) tf32 uint2 pairs in smem.
// Inner loops = pure LDS.64 + mma (no cvt chains). Per block: one (b,h),
// 64 q rows, 256 threads = 8 warps.
// ---------------------------------------------------------------------------
constexpr int FBQ = 64;
constexpr int FBK = 64;
constexpr int QK_ST = 132;   // uint2 stride: (4*lr+lc) mod 16 bijective per half-warp
constexpr int V_ST  = 136;   // uint2 stride: (8*lc+lr) mod 16 bijective per half-warp
constexpr int SS_ST = 68;    // fp32 scores stride
constexpr int FLASH_SMEM_BYTES =
    (FBQ * QK_ST + FBK * QK_ST + FBK * V_ST) * 8 + (FBQ * SS_ST + 3 * FBQ) * 4; // 222,976 B

__global__ __launch_bounds__(256, 1)
void flash_kernel(const float* __restrict__ Qf, const float* __restrict__ Kf,
                  const float* __restrict__ Vf, float* __restrict__ Of)
{
    extern __shared__ char smraw[];
    uint2* Qp = reinterpret_cast<uint2*>(smraw);       // [64][132]
    uint2* Kp = Qp + FBQ * QK_ST;                      // [64][132]
    uint2* Vp = Kp + FBK * QK_ST;                      // [64][136]
    float* Ss = reinterpret_cast<float*>(Vp + FBK * V_ST);   // [64][68]
    float* m_sm = Ss + FBQ * SS_ST;
    float* l_sm = m_sm + FBQ;
    float* a_sm = l_sm + FBQ;

    const int tid = threadIdx.x;
    const int lane = tid & 31;
    const int wid = tid >> 5;
    const int lr = lane >> 2;
    const int lc = lane & 3;

    const int qt = blockIdx.x;
    const int bh = blockIdx.y;
    const int b = bh / NHEADS;
    const int h = bh - b * NHEADS;
    const int hk = h / GRP;

    const float SCALE = 0.0883883476483184f;   // 1/sqrt(128)

    const int wmS = (wid >> 1) * 16;     // scores rows (4 groups)
    const int wnS = (wid & 1) * 32;      // scores cols (2 groups)
    const int wmP = wmS;                 // PV rows
    const int wnP = (wid & 1) * 64;      // PV cols

    // load + scale + split Q tile (once)
    {
        const size_t qbase = ((size_t)(b * SEQ + qt * FBQ)) * NQCOLS + h * HDIM;
#pragma unroll
        for (int it = 0; it < 8; it++) {
            const int f = tid + it * 256;
            const int r = f >> 5;
            const int d = (f & 31) * 4;
            float4 v = *reinterpret_cast<const float4*>(&Qf[qbase + (size_t)r * NQCOLS + d]);
            uint2* qp = &Qp[r * QK_ST + d];
            qp[0] = split2_tf32(v.x * SCALE);
            qp[1] = split2_tf32(v.y * SCALE);
            qp[2] = split2_tf32(v.z * SCALE);
            qp[3] = split2_tf32(v.w * SCALE);
        }
    }
    if (tid < FBQ) { m_sm[tid] = -1e30f; l_sm[tid] = 0.f; }

    // PV accumulators: rows lr, lr+8; cols wnP + nt*8 + {2lc, 2lc+1}
    float acc[8][4];
#pragma unroll
    for (int nt = 0; nt < 8; nt++)
#pragma unroll
        for (int q = 0; q < 4; q++) acc[nt][q] = 0.f;

    for (int kt = 0; kt <= qt; kt++) {
        __syncthreads();    // prior PV done with Kp/Vp/Ss; Q/stats visible iter 0

        // load + split K, V tiles
        {
            const size_t kvbase = ((size_t)(b * SEQ + kt * FBK)) * NKVCOLS + hk * HDIM;
#pragma unroll
            for (int it = 0; it < 8; it++) {
                const int f = tid + it * 256;
                const int r = f >> 5;
                const int d = (f & 31) * 4;
                float4 kv = *reinterpret_cast<const float4*>(&Kf[kvbase + (size_t)r * NKVCOLS + d]);
                uint2* kp = &Kp[r * QK_ST + d];
                kp[0] = split2_tf32(kv.x);
                kp[1] = split2_tf32(kv.y);
                kp[2] = split2_tf32(kv.z);
                kp[3] = split2_tf32(kv.w);
                float4 vv = *reinterpret_cast<const float4*>(&Vf[kvbase + (size_t)r * NKVCOLS + d]);
                uint2* vp = &Vp[r * V_ST + d];
                vp[0] = split2_tf32(vv.x);
                vp[1] = split2_tf32(vv.y);
                vp[2] = split2_tf32(vv.z);
                vp[3] = split2_tf32(vv.w);
            }
        }
        __syncthreads();

        // ---- scores: S = Q K^T (3-term tf32, fragments preloaded) ----
        {
            float cs[4][4];
#pragma unroll
            for (int nt = 0; nt < 4; nt++)
#pragma unroll
                for (int q = 0; q < 4; q++) cs[nt][q] = 0.f;

#pragma unroll
            for (int ks = 0; ks < HDIM / 8; ks++) {
                const uint2 q0 = Qp[(wmS + lr) * QK_ST + ks * 8 + lc];
                const uint2 q1 = Qp[(wmS + lr + 8) * QK_ST + ks * 8 + lc];
                const uint2 q2 = Qp[(wmS + lr) * QK_ST + ks * 8 + lc + 4];
                const uint2 q3 = Qp[(wmS + lr + 8) * QK_ST + ks * 8 + lc + 4];
                const uint32_t ah[4] = {q0.x, q1.x, q2.x, q3.x};
                const uint32_t al[4] = {q0.y, q1.y, q2.y, q3.y};
#pragma unroll
                for (int nt = 0; nt < 4; nt++) {
                    const uint2 b0 = Kp[(wnS + nt * 8 + lr) * QK_ST + ks * 8 + lc];
                    const uint2 b1 = Kp[(wnS + nt * 8 + lr) * QK_ST + ks * 8 + lc + 4];
                    const uint32_t bhv[2] = {b0.x, b1.x};
                    const uint32_t blv[2] = {b0.y, b1.y};
                    mma_tf32(cs[nt], ah, bhv);
                    mma_tf32(cs[nt], ah, blv);
                    mma_tf32(cs[nt], al, bhv);
                }
            }

            // write to smem with causal mask (only diagonal tile needs masking)
            if (kt == qt) {
                const int grow0 = qt * FBQ + wmS + lr;
                const int gcolb = kt * FBK + wnS;
#pragma unroll
                for (int nt = 0; nt < 4; nt++) {
                    const int c = wnS + nt * 8 + lc * 2;
                    const int gc = gcolb + nt * 8 + lc * 2;
                    float v0 = (gc     > grow0) ? -1e30f : cs[nt][0];
                    float v1 = (gc + 1 > grow0) ? -1e30f : cs[nt][1];
                    float v2 = (gc     > grow0 + 8) ? -1e30f : cs[nt][2];
                    float v3 = (gc + 1 > grow0 + 8) ? -1e30f : cs[nt][3];
                    *reinterpret_cast<float2*>(&Ss[(wmS + lr) * SS_ST + c])     = make_float2(v0, v1);
                    *reinterpret_cast<float2*>(&Ss[(wmS + lr + 8) * SS_ST + c]) = make_float2(v2, v3);
                }
            } else {
#pragma unroll
                for (int nt = 0; nt < 4; nt++) {
                    const int c = wnS + nt * 8 + lc * 2;
                    *reinterpret_cast<float2*>(&Ss[(wmS + lr) * SS_ST + c])     = make_float2(cs[nt][0], cs[nt][1]);
                    *reinterpret_cast<float2*>(&Ss[(wmS + lr + 8) * SS_ST + c]) = make_float2(cs[nt][2], cs[nt][3]);
                }
            }
        }
        __syncthreads();

        // ---- online softmax: 4 threads per row ----
        {
            const int row = tid >> 2;
            const int g = tid & 3;
            float* Sr = &Ss[row * SS_ST + g * 16];
            float mloc = -1e30f;
#pragma unroll
            for (int jj = 0; jj < 16; jj++) mloc = fmaxf(mloc, Sr[jj]);
            mloc = fmaxf(mloc, __shfl_xor_sync(0xffffffffu, mloc, 1));
            mloc = fmaxf(mloc, __shfl_xor_sync(0xffffffffu, mloc, 2));
            const float mold = m_sm[row];
            const float mnew = fmaxf(mold, mloc);
            const float alpha = __expf(mold - mnew);
            float ssum = 0.f;
#pragma unroll
            for (int jj = 0; jj < 16; jj++) {
                float p = __expf(Sr[jj] - mnew);
                Sr[jj] = p;
                ssum += p;
            }
            ssum += __shfl_xor_sync(0xffffffffu, ssum, 1);
            ssum += __shfl_xor_sync(0xffffffffu, ssum, 2);
            if (g == 0) {
                m_sm[row] = mnew;
                l_sm[row] = l_sm[row] * alpha + ssum;
                a_sm[row] = alpha;
            }
        }
        __syncthreads();

        // ---- PV: O += P V (3-term; V preloaded split, P split in-loop) ----
        {
            const float al0 = a_sm[wmP + lr];
            const float al1 = a_sm[wmP + lr + 8];
#pragma unroll
            for (int nt = 0; nt < 8; nt++) {
                acc[nt][0] *= al0; acc[nt][1] *= al0;
                acc[nt][2] *= al1; acc[nt][3] *= al1;
            }

#pragma unroll
            for (int ks = 0; ks < FBK / 8; ks++) {
                uint32_t ph[4], pl[4];
                split_tf32(Ss[(wmP + lr) * SS_ST + ks * 8 + lc],       ph[0], pl[0]);
                split_tf32(Ss[(wmP + lr + 8) * SS_ST + ks * 8 + lc],   ph[1], pl[1]);
                split_tf32(Ss[(wmP + lr) * SS_ST + ks * 8 + lc + 4],   ph[2], pl[2]);
                split_tf32(Ss[(wmP + lr + 8) * SS_ST + ks * 8 + lc + 4], ph[3], pl[3]);
#pragma unroll
                for (int nt = 0; nt < 8; nt++) {
                    const int n = wnP + nt * 8 + lr;
                    const uint2 v0 = Vp[(ks * 8 + lc) * V_ST + n];
                    const uint2 v1 = Vp[(ks * 8 + lc + 4) * V_ST + n];
                    const uint32_t vh[2] = {v0.x, v1.x};
                    const uint32_t vl[2] = {v0.y, v1.y};
                    mma_tf32(acc[nt], ph, vh);
                    mma_tf32(acc[nt], ph, vl);
                    mma_tf32(acc[nt], pl, vh);
                }
            }
        }
    }

    // epilogue
    __syncthreads();
    {
        const float inv0 = 1.0f / l_sm[wmP + lr];
        const float inv1 = 1.0f / l_sm[wmP + lr + 8];
        const size_t ob0 = ((size_t)(b * SEQ + qt * FBQ + wmP + lr)) * NQCOLS + h * HDIM;
        const size_t ob1 = ((size_t)(b * SEQ + qt * FBQ + wmP + lr + 8)) * NQCOLS + h * HDIM;
#pragma unroll
        for (int nt = 0; nt < 8; nt++) {
            const int c = wnP + nt * 8 + lc * 2;
            *reinterpret_cast<float2*>(&Of[ob0 + c]) =
                make_float2(acc[nt][0] * inv0, acc[nt][1] * inv0);
            *reinterpret_cast<float2*>(&Of[ob1 + c]) =
                make_float2(acc[nt][2] * inv1, acc[nt][3] * inv1);
        }
    }
}

// ---------------------------------------------------------------------------
// Launch
// ---------------------------------------------------------------------------
extern "C" void kernel_launch(void* const* d_in, const int* in_sizes, int n_in,
                              void* d_out, int out_size)
{
    (void)in_sizes; (void)n_in; (void)out_size;
    const float* X        = (const float*)d_in[0];
    const float* cosv     = (const float*)d_in[1];
    const float* sinv     = (const float*)d_in[2];
    // d_in[3] = position_ids (arange(S) broadcast; computed analytically)
    // d_in[4] = attention_mask (causal; applied analytically)
    const float* Wq       = (const float*)d_in[5];
    const float* Wk       = (const float*)d_in[6];
    const float* Wv       = (const float*)d_in[7];
    const float* Wo       = (const float*)d_in[8];
    float* out            = (float*)d_out;

    float *qp, *kp, *vp, *aop;
    cudaGetSymbolAddress((void**)&qp,  g_Q);
    cudaGetSymbolAddress((void**)&kp,  g_K);
    cudaGetSymbolAddress((void**)&vp,  g_V);
    cudaGetSymbolAddress((void**)&aop, g_AO);

    // QKV projections (mma.sync tf32)
    tgemm_nt_tf32<<<dim3(NQCOLS / TBN, MROWS / TBM), 256>>>(X, Wq, qp, NQCOLS, HID);
    tgemm_nt_tf32<<<dim3(NKVCOLS / TBN, MROWS / TBM), 256>>>(X, Wk, kp, NKVCOLS, HID);
    tgemm_nt_tf32<<<dim3(NKVCOLS / TBN, MROWS / TBM), 256>>>(X, Wv, vp, NKVCOLS, HID);

    // RoPE on Q and K
    {
        int totq = MROWS * (NQCOLS / 2);
        int totk = MROWS * (NKVCOLS / 2);
        rope_kernel<<<(totq + 255) / 256, 256>>>(qp, NQCOLS, cosv, sinv);
        rope_kernel<<<(totk + 255) / 256, 256>>>(kp, NKVCOLS, cosv, sinv);
    }

    // Flash attention (pre-split smem, mma.sync tf32)
    cudaFuncSetAttribute(flash_kernel, cudaFuncAttributeMaxDynamicSharedMemorySize,
                         FLASH_SMEM_BYTES);
    flash_kernel<<<dim3(SEQ / FBQ, BATCH * NHEADS), 256, FLASH_SMEM_BYTES>>>(qp, kp, vp, aop);

    // Output projection -> d_out (mma.sync tf32)
    tgemm_nt_tf32<<<dim3(HID / TBN, MROWS / TBM), 256>>>(aop, Wo, out, HID, NQCOLS);
}

// round 7
// speedup vs baseline: 1.1287x; 1.1287x over previous
#include <cuda_runtime.h>
#include <cuda_fp16.h>
#include <math.h>
#include <stdint.h>

// Problem dims
constexpr int BATCH = 2;
constexpr int SEQ   = 2048;
constexpr int HID   = 4096;
constexpr int NHEADS = 32;
constexpr int NKVH   = 8;
constexpr int HDIM   = 128;
constexpr int GRP    = NHEADS / NKVH;          // 4
constexpr int MROWS  = BATCH * SEQ;            // 4096
constexpr int NQCOLS = NHEADS * HDIM;          // 4096
constexpr int NKVCOLS = NKVH * HDIM;           // 1024

// Scratch (device globals; no runtime allocation allowed)
__device__ float g_Q[(size_t)MROWS * NQCOLS];
__device__ float g_K[(size_t)MROWS * NKVCOLS];
__device__ float g_V[(size_t)MROWS * NKVCOLS];
__device__ float g_AO[(size_t)MROWS * NQCOLS];

// ---------------------------------------------------------------------------
// fp16 mma helper: m16n8k16, f32 accumulate.
// A frag: a0=(lr,2lc:2lc+1) a1=(lr+8,..) a2=(lr,2lc+8:+9) a3=(lr+8,..)
// B frag: b0=(k=2lc:2lc+1,n=lr) b1=(k=2lc+8:+9,n=lr)
// C frag: c0,c1=(lr, 2lc,2lc+1) c2,c3=(lr+8, ..)
// ---------------------------------------------------------------------------
__device__ __forceinline__ void mma_f16(float c[4], const uint32_t a[4], const uint32_t b[2]) {
    asm volatile(
        "mma.sync.aligned.m16n8k16.row.col.f32.f16.f16.f32 "
        "{%0,%1,%2,%3}, {%4,%5,%6,%7}, {%8,%9}, {%0,%1,%2,%3};\n"
        : "+f"(c[0]), "+f"(c[1]), "+f"(c[2]), "+f"(c[3])
        : "r"(a[0]), "r"(a[1]), "r"(a[2]), "r"(a[3]), "r"(b[0]), "r"(b[1]));
}

// split a float pair into hi(fp16x2) and lo(fp16x2) packed regs
__device__ __forceinline__ void split_pair(float x0, float x1, uint32_t& hi, uint32_t& lo) {
    __half2 h = __float22half2_rn(make_float2(x0, x1));
    float l0 = x0 - __low2float(h);
    float l1 = x1 - __high2float(h);
    __half2 l = __float22half2_rn(make_float2(l0, l1));
    hi = *reinterpret_cast<uint32_t*>(&h);
    lo = *reinterpret_cast<uint32_t*>(&l);
}

// ---------------------------------------------------------------------------
// fp16 3-term GEMM NT: C[M,N] = A[M,K] * B[N,K]^T (row-major fp32 I/O).
// Block 128x128x32, 8 warps of 32x64. Stride 40 halves => conflict-free frag LDS.
// Accuracy ~fp32 (error ~2^-22 per product).
// ---------------------------------------------------------------------------
constexpr int TBM = 128, TBN = 128, TBK = 32;
constexpr int GST = 40;    // smem stride in halves (32 data + 8 pad)

__global__ __launch_bounds__(256, 1)
void hgemm_nt_3t(const float* __restrict__ A, const float* __restrict__ Bm,
                 float* __restrict__ C, int Ndim, int Kdim)
{
    __shared__ __half Ah[TBM * GST];
    __shared__ __half Al[TBM * GST];
    __shared__ __half Bh[TBN * GST];
    __shared__ __half Bl[TBN * GST];

    const int tid  = threadIdx.x;
    const int lane = tid & 31;
    const int wid  = tid >> 5;
    const int wm   = (wid >> 1) * 32;
    const int wn   = (wid & 1) * 64;
    const int lr   = lane >> 2;
    const int lc   = lane & 3;
    const int bm0  = blockIdx.y * TBM;
    const int bn0  = blockIdx.x * TBN;

    const int grow = tid >> 3;           // 0..31 (+i*32)
    const int gkc  = (tid & 7) * 4;      // 0..28

    const float* Ap = A  + (size_t)(bm0 + grow) * Kdim + gkc;
    const float* Bp = Bm + (size_t)(bn0 + grow) * Kdim + gkc;

    float4 pa[4], pb[4];
#pragma unroll
    for (int i = 0; i < 4; i++) {
        pa[i] = *reinterpret_cast<const float4*>(Ap + (size_t)i * 32 * Kdim);
        pb[i] = *reinterpret_cast<const float4*>(Bp + (size_t)i * 32 * Kdim);
    }

    float cfr[2][8][4];
#pragma unroll
    for (int mt = 0; mt < 2; mt++)
#pragma unroll
        for (int nt = 0; nt < 8; nt++)
#pragma unroll
            for (int q = 0; q < 4; q++) cfr[mt][nt][q] = 0.f;

    int k0 = 0;
    for (;;) {
        // store prefetched tile to smem (hi/lo fp16)
#pragma unroll
        for (int i = 0; i < 4; i++) {
            const int r = grow + i * 32;
            uint32_t h0, l0, h1, l1;
            split_pair(pa[i].x, pa[i].y, h0, l0);
            split_pair(pa[i].z, pa[i].w, h1, l1);
            *reinterpret_cast<uint2*>(&Ah[r * GST + gkc]) = make_uint2(h0, h1);
            *reinterpret_cast<uint2*>(&Al[r * GST + gkc]) = make_uint2(l0, l1);
            split_pair(pb[i].x, pb[i].y, h0, l0);
            split_pair(pb[i].z, pb[i].w, h1, l1);
            *reinterpret_cast<uint2*>(&Bh[r * GST + gkc]) = make_uint2(h0, h1);
            *reinterpret_cast<uint2*>(&Bl[r * GST + gkc]) = make_uint2(l0, l1);
        }
        __syncthreads();

        k0 += TBK;
        const bool more = (k0 < Kdim);
        if (more) {
#pragma unroll
            for (int i = 0; i < 4; i++) {
                pa[i] = *reinterpret_cast<const float4*>(Ap + k0 + (size_t)i * 32 * Kdim);
                pb[i] = *reinterpret_cast<const float4*>(Bp + k0 + (size_t)i * 32 * Kdim);
            }
        }

        // compute: 2 k16-steps
#pragma unroll
        for (int ks = 0; ks < 2; ks++) {
            const int kb = ks * 16 + 2 * lc;
            uint32_t ah[2][4], al[2][4];
#pragma unroll
            for (int mt = 0; mt < 2; mt++) {
                const int r = wm + mt * 16 + lr;
                ah[mt][0] = *reinterpret_cast<const uint32_t*>(&Ah[r * GST + kb]);
                ah[mt][1] = *reinterpret_cast<const uint32_t*>(&Ah[(r + 8) * GST + kb]);
                ah[mt][2] = *reinterpret_cast<const uint32_t*>(&Ah[r * GST + kb + 8]);
                ah[mt][3] = *reinterpret_cast<const uint32_t*>(&Ah[(r + 8) * GST + kb + 8]);
                al[mt][0] = *reinterpret_cast<const uint32_t*>(&Al[r * GST + kb]);
                al[mt][1] = *reinterpret_cast<const uint32_t*>(&Al[(r + 8) * GST + kb]);
                al[mt][2] = *reinterpret_cast<const uint32_t*>(&Al[r * GST + kb + 8]);
                al[mt][3] = *reinterpret_cast<const uint32_t*>(&Al[(r + 8) * GST + kb + 8]);
            }
#pragma unroll
            for (int nt = 0; nt < 8; nt++) {
                const int n = wn + nt * 8 + lr;
                uint32_t bh[2], bl[2];
                bh[0] = *reinterpret_cast<const uint32_t*>(&Bh[n * GST + kb]);
                bh[1] = *reinterpret_cast<const uint32_t*>(&Bh[n * GST + kb + 8]);
                bl[0] = *reinterpret_cast<const uint32_t*>(&Bl[n * GST + kb]);
                bl[1] = *reinterpret_cast<const uint32_t*>(&Bl[n * GST + kb + 8]);
#pragma unroll
                for (int mt = 0; mt < 2; mt++) {
                    mma_f16(cfr[mt][nt], ah[mt], bh);
                    mma_f16(cfr[mt][nt], ah[mt], bl);
                    mma_f16(cfr[mt][nt], al[mt], bh);
                }
            }
        }

        if (!more) break;
        __syncthreads();
    }

#pragma unroll
    for (int mt = 0; mt < 2; mt++)
#pragma unroll
        for (int nt = 0; nt < 8; nt++) {
            const int row = bm0 + wm + mt * 16 + lr;
            const int col = bn0 + wn + nt * 8 + lc * 2;
            *reinterpret_cast<float2*>(&C[(size_t)row * Ndim + col]) =
                make_float2(cfr[mt][nt][0], cfr[mt][nt][1]);
            *reinterpret_cast<float2*>(&C[(size_t)(row + 8) * Ndim + col]) =
                make_float2(cfr[mt][nt][2], cfr[mt][nt][3]);
        }
}

// ---------------------------------------------------------------------------
// Flash attention fp16-3term, RoPE fused into Q/K tile loads.
// Per block: one (b,h), 64 q rows, 256 threads = 8 warps, 2 CTAs/SM.
// Q,K: hi+lo fp16 (exact-ish); V: hi only; P: exact via hi+lo x V_hi.
// ---------------------------------------------------------------------------
constexpr int FBQ = 64;
constexpr int FBK = 64;
constexpr int H_ST  = 136;   // halves stride (128 data + 8 pad): banks 4*lr+lc
constexpr int SS_ST = 68;    // f32 scores stride
constexpr int FLASH_SMEM_BYTES =
    5 * (64 * H_ST * 2) + (FBQ * SS_ST + 3 * FBQ) * 4;   // 5 half-arrays + S + stats = 105216

__global__ __launch_bounds__(256, 2)
void flash_kernel(const float* __restrict__ Qf, const float* __restrict__ Kf,
                  const float* __restrict__ Vf, float* __restrict__ Of,
                  const float* __restrict__ cosv, const float* __restrict__ sinv)
{
    extern __shared__ char smraw[];
    __half* Qh = reinterpret_cast<__half*>(smraw);            // [64][136]
    __half* Ql = Qh + 64 * H_ST;
    __half* Kh = Ql + 64 * H_ST;
    __half* Kl = Kh + 64 * H_ST;
    __half* Vh = Kl + 64 * H_ST;                               // [kv][d]
    float*  Ss = reinterpret_cast<float*>(Vh + 64 * H_ST);     // [64][68]
    float* m_sm = Ss + FBQ * SS_ST;
    float* l_sm = m_sm + FBQ;
    float* a_sm = l_sm + FBQ;

    const int tid = threadIdx.x;
    const int lane = tid & 31;
    const int wid = tid >> 5;
    const int lr = lane >> 2;
    const int lc = lane & 3;

    const int qt = blockIdx.x;
    const int bh = blockIdx.y;
    const int b = bh / NHEADS;
    const int h = bh - b * NHEADS;
    const int hk = h / GRP;

    const float SCALE = 0.0883883476483184f;   // 1/sqrt(128), applied post-mma

    const int wmS = (wid >> 1) * 16;     // scores rows
    const int wnS = (wid & 1) * 32;      // scores cols
    const int wmP = wmS;                 // PV rows
    const int wnP = (wid & 1) * 64;      // PV cols

    // ---- load Q tile with fused RoPE, split to hi/lo fp16 ----
    {
        const size_t qbase = ((size_t)(b * SEQ + qt * FBQ)) * NQCOLS + h * HDIM;
#pragma unroll
        for (int it = 0; it < 8; it++) {
            const int f = tid + it * 256;
            const int r = f >> 5;
            const int d = (f & 31) * 4;
            const int t = qt * FBQ + r;
            float4 v = *reinterpret_cast<const float4*>(&Qf[qbase + (size_t)r * NQCOLS + d]);
            const float c0 = cosv[t * 64 + d / 2],     s0 = sinv[t * 64 + d / 2];
            const float c1 = cosv[t * 64 + d / 2 + 1], s1 = sinv[t * 64 + d / 2 + 1];
            float x0 = v.x * c0 - v.y * s0, x1 = v.x * s0 + v.y * c0;
            float x2 = v.z * c1 - v.w * s1, x3 = v.z * s1 + v.w * c1;
            uint32_t h0, l0, h1, l1;
            split_pair(x0, x1, h0, l0);
            split_pair(x2, x3, h1, l1);
            *reinterpret_cast<uint2*>(&Qh[r * H_ST + d]) = make_uint2(h0, h1);
            *reinterpret_cast<uint2*>(&Ql[r * H_ST + d]) = make_uint2(l0, l1);
        }
    }
    if (tid < FBQ) { m_sm[tid] = -1e30f; l_sm[tid] = 0.f; }

    float acc[8][4];
#pragma unroll
    for (int nt = 0; nt < 8; nt++)
#pragma unroll
        for (int q = 0; q < 4; q++) acc[nt][q] = 0.f;

    for (int kt = 0; kt <= qt; kt++) {
        __syncthreads();

        // ---- load K (roped, hi/lo) and V (hi) tiles ----
        {
            const size_t kvbase = ((size_t)(b * SEQ + kt * FBK)) * NKVCOLS + hk * HDIM;
#pragma unroll
            for (int it = 0; it < 8; it++) {
                const int f = tid + it * 256;
                const int r = f >> 5;
                const int d = (f & 31) * 4;
                const int t = kt * FBK + r;
                float4 kv = *reinterpret_cast<const float4*>(&Kf[kvbase + (size_t)r * NKVCOLS + d]);
                const float c0 = cosv[t * 64 + d / 2],     s0 = sinv[t * 64 + d / 2];
                const float c1 = cosv[t * 64 + d / 2 + 1], s1 = sinv[t * 64 + d / 2 + 1];
                float x0 = kv.x * c0 - kv.y * s0, x1 = kv.x * s0 + kv.y * c0;
                float x2 = kv.z * c1 - kv.w * s1, x3 = kv.z * s1 + kv.w * c1;
                uint32_t h0, l0, h1, l1;
                split_pair(x0, x1, h0, l0);
                split_pair(x2, x3, h1, l1);
                *reinterpret_cast<uint2*>(&Kh[r * H_ST + d]) = make_uint2(h0, h1);
                *reinterpret_cast<uint2*>(&Kl[r * H_ST + d]) = make_uint2(l0, l1);
                float4 vv = *reinterpret_cast<const float4*>(&Vf[kvbase + (size_t)r * NKVCOLS + d]);
                __half2 vh0 = __float22half2_rn(make_float2(vv.x, vv.y));
                __half2 vh1 = __float22half2_rn(make_float2(vv.z, vv.w));
                *reinterpret_cast<uint2*>(&Vh[r * H_ST + d]) =
                    make_uint2(*reinterpret_cast<uint32_t*>(&vh0), *reinterpret_cast<uint32_t*>(&vh1));
            }
        }
        __syncthreads();

        // ---- scores: S = Q K^T, fp16 3-term ----
        {
            float cs[4][4];
#pragma unroll
            for (int nt = 0; nt < 4; nt++)
#pragma unroll
                for (int q = 0; q < 4; q++) cs[nt][q] = 0.f;

#pragma unroll
            for (int ks = 0; ks < HDIM / 16; ks++) {
                const int kb = ks * 16 + 2 * lc;
                uint32_t qh[4], ql[4];
                qh[0] = *reinterpret_cast<const uint32_t*>(&Qh[(wmS + lr) * H_ST + kb]);
                qh[1] = *reinterpret_cast<const uint32_t*>(&Qh[(wmS + lr + 8) * H_ST + kb]);
                qh[2] = *reinterpret_cast<const uint32_t*>(&Qh[(wmS + lr) * H_ST + kb + 8]);
                qh[3] = *reinterpret_cast<const uint32_t*>(&Qh[(wmS + lr + 8) * H_ST + kb + 8]);
                ql[0] = *reinterpret_cast<const uint32_t*>(&Ql[(wmS + lr) * H_ST + kb]);
                ql[1] = *reinterpret_cast<const uint32_t*>(&Ql[(wmS + lr + 8) * H_ST + kb]);
                ql[2] = *reinterpret_cast<const uint32_t*>(&Ql[(wmS + lr) * H_ST + kb + 8]);
                ql[3] = *reinterpret_cast<const uint32_t*>(&Ql[(wmS + lr + 8) * H_ST + kb + 8]);
#pragma unroll
                for (int nt = 0; nt < 4; nt++) {
                    const int n = wnS + nt * 8 + lr;
                    uint32_t kh[2], kl[2];
                    kh[0] = *reinterpret_cast<const uint32_t*>(&Kh[n * H_ST + kb]);
                    kh[1] = *reinterpret_cast<const uint32_t*>(&Kh[n * H_ST + kb + 8]);
                    kl[0] = *reinterpret_cast<const uint32_t*>(&Kl[n * H_ST + kb]);
                    kl[1] = *reinterpret_cast<const uint32_t*>(&Kl[n * H_ST + kb + 8]);
                    mma_f16(cs[nt], qh, kh);
                    mma_f16(cs[nt], qh, kl);
                    mma_f16(cs[nt], ql, kh);
                }
            }

            // scale + (diagonal-only) causal mask + store
            if (kt == qt) {
                const int grow0 = qt * FBQ + wmS + lr;
                const int gcolb = kt * FBK + wnS;
#pragma unroll
                for (int nt = 0; nt < 4; nt++) {
                    const int c = wnS + nt * 8 + lc * 2;
                    const int gc = gcolb + nt * 8 + lc * 2;
                    float v0 = (gc     > grow0) ? -1e30f : cs[nt][0] * SCALE;
                    float v1 = (gc + 1 > grow0) ? -1e30f : cs[nt][1] * SCALE;
                    float v2 = (gc     > grow0 + 8) ? -1e30f : cs[nt][2] * SCALE;
                    float v3 = (gc + 1 > grow0 + 8) ? -1e30f : cs[nt][3] * SCALE;
                    *reinterpret_cast<float2*>(&Ss[(wmS + lr) * SS_ST + c])     = make_float2(v0, v1);
                    *reinterpret_cast<float2*>(&Ss[(wmS + lr + 8) * SS_ST + c]) = make_float2(v2, v3);
                }
            } else {
#pragma unroll
                for (int nt = 0; nt < 4; nt++) {
                    const int c = wnS + nt * 8 + lc * 2;
                    *reinterpret_cast<float2*>(&Ss[(wmS + lr) * SS_ST + c]) =
                        make_float2(cs[nt][0] * SCALE, cs[nt][1] * SCALE);
                    *reinterpret_cast<float2*>(&Ss[(wmS + lr + 8) * SS_ST + c]) =
                        make_float2(cs[nt][2] * SCALE, cs[nt][3] * SCALE);
                }
            }
        }
        __syncthreads();

        // ---- online softmax: 4 threads per row ----
        {
            const int row = tid >> 2;
            const int g = tid & 3;
            float* Sr = &Ss[row * SS_ST + g * 16];
            float mloc = -1e30f;
#pragma unroll
            for (int jj = 0; jj < 16; jj++) mloc = fmaxf(mloc, Sr[jj]);
            mloc = fmaxf(mloc, __shfl_xor_sync(0xffffffffu, mloc, 1));
            mloc = fmaxf(mloc, __shfl_xor_sync(0xffffffffu, mloc, 2));
            const float mold = m_sm[row];
            const float mnew = fmaxf(mold, mloc);
            const float alpha = __expf(mold - mnew);
            float ssum = 0.f;
#pragma unroll
            for (int jj = 0; jj < 16; jj++) {
                float p = __expf(Sr[jj] - mnew);
                Sr[jj] = p;
                ssum += p;
            }
            ssum += __shfl_xor_sync(0xffffffffu, ssum, 1);
            ssum += __shfl_xor_sync(0xffffffffu, ssum, 2);
            if (g == 0) {
                m_sm[row] = mnew;
                l_sm[row] = l_sm[row] * alpha + ssum;
                a_sm[row] = alpha;
            }
        }
        __syncthreads();

        // ---- PV: O += P V  (P exact via hi+lo; V hi-only) ----
        {
            const float al0 = a_sm[wmP + lr];
            const float al1 = a_sm[wmP + lr + 8];
#pragma unroll
            for (int nt = 0; nt < 8; nt++) {
                acc[nt][0] *= al0; acc[nt][1] *= al0;
                acc[nt][2] *= al1; acc[nt][3] *= al1;
            }

#pragma unroll
            for (int ks = 0; ks < FBK / 16; ks++) {
                const int kb = ks * 16 + 2 * lc;
                float2 p00 = *reinterpret_cast<const float2*>(&Ss[(wmP + lr) * SS_ST + kb]);
                float2 p01 = *reinterpret_cast<const float2*>(&Ss[(wmP + lr + 8) * SS_ST + kb]);
                float2 p10 = *reinterpret_cast<const float2*>(&Ss[(wmP + lr) * SS_ST + kb + 8]);
                float2 p11 = *reinterpret_cast<const float2*>(&Ss[(wmP + lr + 8) * SS_ST + kb + 8]);
                uint32_t ph[4], pl[4];
                split_pair(p00.x, p00.y, ph[0], pl[0]);
                split_pair(p01.x, p01.y, ph[1], pl[1]);
                split_pair(p10.x, p10.y, ph[2], pl[2]);
                split_pair(p11.x, p11.y, ph[3], pl[3]);
#pragma unroll
                for (int nt = 0; nt < 8; nt++) {
                    const int n = wnP + nt * 8 + lr;
                    __half2 b0 = __halves2half2(Vh[(kb + 0) * H_ST + n], Vh[(kb + 1) * H_ST + n]);
                    __half2 b1 = __halves2half2(Vh[(kb + 8) * H_ST + n], Vh[(kb + 9) * H_ST + n]);
                    uint32_t vb[2] = {*reinterpret_cast<uint32_t*>(&b0),
                                      *reinterpret_cast<uint32_t*>(&b1)};
                    mma_f16(acc[nt], ph, vb);
                    mma_f16(acc[nt], pl, vb);
                }
            }
        }
    }

    // epilogue
    __syncthreads();
    {
        const float inv0 = 1.0f / l_sm[wmP + lr];
        const float inv1 = 1.0f / l_sm[wmP + lr + 8];
        const size_t ob0 = ((size_t)(b * SEQ + qt * FBQ + wmP + lr)) * NQCOLS + h * HDIM;
        const size_t ob1 = ((size_t)(b * SEQ + qt * FBQ + wmP + lr + 8)) * NQCOLS + h * HDIM;
#pragma unroll
        for (int nt = 0; nt < 8; nt++) {
            const int c = wnP + nt * 8 + lc * 2;
            *reinterpret_cast<float2*>(&Of[ob0 + c]) =
                make_float2(acc[nt][0] * inv0, acc[nt][1] * inv0);
            *reinterpret_cast<float2*>(&Of[ob1 + c]) =
                make_float2(acc[nt][2] * inv1, acc[nt][3] * inv1);
        }
    }
}

// ---------------------------------------------------------------------------
// Launch
// ---------------------------------------------------------------------------
extern "C" void kernel_launch(void* const* d_in, const int* in_sizes, int n_in,
                              void* d_out, int out_size)
{
    (void)in_sizes; (void)n_in; (void)out_size;
    const float* X        = (const float*)d_in[0];
    const float* cosv     = (const float*)d_in[1];
    const float* sinv     = (const float*)d_in[2];
    // d_in[3] = position_ids (arange(S) broadcast; computed analytically)
    // d_in[4] = attention_mask (causal; applied analytically)
    const float* Wq       = (const float*)d_in[5];
    const float* Wk       = (const float*)d_in[6];
    const float* Wv       = (const float*)d_in[7];
    const float* Wo       = (const float*)d_in[8];
    float* out            = (float*)d_out;

    float *qp, *kp, *vp, *aop;
    cudaGetSymbolAddress((void**)&qp,  g_Q);
    cudaGetSymbolAddress((void**)&kp,  g_K);
    cudaGetSymbolAddress((void**)&vp,  g_V);
    cudaGetSymbolAddress((void**)&aop, g_AO);

    // QKV projections (fp16 3-term tensor cores)
    hgemm_nt_3t<<<dim3(NQCOLS / TBN, MROWS / TBM), 256>>>(X, Wq, qp, NQCOLS, HID);
    hgemm_nt_3t<<<dim3(NKVCOLS / TBN, MROWS / TBM), 256>>>(X, Wk, kp, NKVCOLS, HID);
    hgemm_nt_3t<<<dim3(NKVCOLS / TBN, MROWS / TBM), 256>>>(X, Wv, vp, NKVCOLS, HID);

    // Flash attention (RoPE fused into Q/K loads)
    cudaFuncSetAttribute(flash_kernel, cudaFuncAttributeMaxDynamicSharedMemorySize,
                         FLASH_SMEM_BYTES);
    flash_kernel<<<dim3(SEQ / FBQ, BATCH * NHEADS), 256, FLASH_SMEM_BYTES>>>(
        qp, kp, vp, aop, cosv, sinv);

    // Output projection -> d_out
    hgemm_nt_3t<<<dim3(HID / TBN, MROWS / TBM), 256>>>(aop, Wo, out, HID, NQCOLS);
}

// round 8
// speedup vs baseline: 1.3509x; 1.1969x over previous
#include <cuda_runtime.h>
#include <cuda_fp16.h>
#include <math.h>
#include <stdint.h>

// Problem dims
constexpr int BATCH = 2;
constexpr int SEQ   = 2048;
constexpr int HID   = 4096;
constexpr int NHEADS = 32;
constexpr int NKVH   = 8;
constexpr int HDIM   = 128;
constexpr int GRP    = NHEADS / NKVH;          // 4
constexpr int MROWS  = BATCH * SEQ;            // 4096
constexpr int NQCOLS = NHEADS * HDIM;          // 4096
constexpr int NKVCOLS = NKVH * HDIM;           // 1024

// Scratch (device globals; no runtime allocation allowed)
__device__ float g_Q[(size_t)MROWS * NQCOLS];
__device__ float g_K[(size_t)MROWS * NKVCOLS];
__device__ float g_V[(size_t)MROWS * NKVCOLS];
__device__ float g_AO[(size_t)MROWS * NQCOLS];

// ---------------------------------------------------------------------------
// fp16 mma helper: m16n8k16, f32 accumulate.
// ---------------------------------------------------------------------------
__device__ __forceinline__ void mma_f16(float c[4], const uint32_t a[4], const uint32_t b[2]) {
    asm volatile(
        "mma.sync.aligned.m16n8k16.row.col.f32.f16.f16.f32 "
        "{%0,%1,%2,%3}, {%4,%5,%6,%7}, {%8,%9}, {%0,%1,%2,%3};\n"
        : "+f"(c[0]), "+f"(c[1]), "+f"(c[2]), "+f"(c[3])
        : "r"(a[0]), "r"(a[1]), "r"(a[2]), "r"(a[3]), "r"(b[0]), "r"(b[1]));
}

// split a float pair into hi(fp16x2) and lo(fp16x2) packed regs
__device__ __forceinline__ void split_pair(float x0, float x1, uint32_t& hi, uint32_t& lo) {
    __half2 h = __float22half2_rn(make_float2(x0, x1));
    float l0 = x0 - __low2float(h);
    float l1 = x1 - __high2float(h);
    __half2 l = __float22half2_rn(make_float2(l0, l1));
    hi = *reinterpret_cast<uint32_t*>(&h);
    lo = *reinterpret_cast<uint32_t*>(&l);
}

__device__ __forceinline__ uint32_t round_pair(float x0, float x1) {
    __half2 h = __float22half2_rn(make_float2(x0, x1));
    return *reinterpret_cast<uint32_t*>(&h);
}

// ---------------------------------------------------------------------------
// fp16 2-term GEMM NT: C = A*B^T with A rounded to fp16, B split hi/lo.
// C ≈ Ah*Bh + Ah*Bl  (error = A_lo·B ~ 2^-11.5 relative — half of tf32 1-pass).
// Block 128x128x32, 8 warps of 32x64, 2 CTAs/SM. Stride 40 halves: conflict-free.
// ---------------------------------------------------------------------------
constexpr int TBM = 128, TBN = 128, TBK = 32;
constexpr int GST = 40;    // smem stride in halves (32 data + 8 pad)

__global__ __launch_bounds__(256, 2)
void hgemm_nt_2t(const float* __restrict__ A, const float* __restrict__ Bm,
                 float* __restrict__ C, int Ndim, int Kdim)
{
    __shared__ __half Ah[TBM * GST];
    __shared__ __half Bh[TBN * GST];
    __shared__ __half Bl[TBN * GST];

    const int tid  = threadIdx.x;
    const int lane = tid & 31;
    const int wid  = tid >> 5;
    const int wm   = (wid >> 1) * 32;
    const int wn   = (wid & 1) * 64;
    const int lr   = lane >> 2;
    const int lc   = lane & 3;
    const int bm0  = blockIdx.y * TBM;
    const int bn0  = blockIdx.x * TBN;

    const int grow = tid >> 3;           // 0..31 (+i*32)
    const int gkc  = (tid & 7) * 4;      // 0..28

    const float* Ap = A  + (size_t)(bm0 + grow) * Kdim + gkc;
    const float* Bp = Bm + (size_t)(bn0 + grow) * Kdim + gkc;

    float4 pa[4], pb[4];
#pragma unroll
    for (int i = 0; i < 4; i++) {
        pa[i] = *reinterpret_cast<const float4*>(Ap + (size_t)i * 32 * Kdim);
        pb[i] = *reinterpret_cast<const float4*>(Bp + (size_t)i * 32 * Kdim);
    }

    float cfr[2][8][4];
#pragma unroll
    for (int mt = 0; mt < 2; mt++)
#pragma unroll
        for (int nt = 0; nt < 8; nt++)
#pragma unroll
            for (int q = 0; q < 4; q++) cfr[mt][nt][q] = 0.f;

    int k0 = 0;
    for (;;) {
        // store prefetched tile to smem
#pragma unroll
        for (int i = 0; i < 4; i++) {
            const int r = grow + i * 32;
            *reinterpret_cast<uint2*>(&Ah[r * GST + gkc]) =
                make_uint2(round_pair(pa[i].x, pa[i].y), round_pair(pa[i].z, pa[i].w));
            uint32_t h0, l0, h1, l1;
            split_pair(pb[i].x, pb[i].y, h0, l0);
            split_pair(pb[i].z, pb[i].w, h1, l1);
            *reinterpret_cast<uint2*>(&Bh[r * GST + gkc]) = make_uint2(h0, h1);
            *reinterpret_cast<uint2*>(&Bl[r * GST + gkc]) = make_uint2(l0, l1);
        }
        __syncthreads();

        k0 += TBK;
        const bool more = (k0 < Kdim);
        if (more) {
#pragma unroll
            for (int i = 0; i < 4; i++) {
                pa[i] = *reinterpret_cast<const float4*>(Ap + k0 + (size_t)i * 32 * Kdim);
                pb[i] = *reinterpret_cast<const float4*>(Bp + k0 + (size_t)i * 32 * Kdim);
            }
        }

        // compute: 2 k16-steps, 2 mmas per (mt,nt)
#pragma unroll
        for (int ks = 0; ks < 2; ks++) {
            const int kb = ks * 16 + 2 * lc;
            uint32_t ah[2][4];
#pragma unroll
            for (int mt = 0; mt < 2; mt++) {
                const int r = wm + mt * 16 + lr;
                ah[mt][0] = *reinterpret_cast<const uint32_t*>(&Ah[r * GST + kb]);
                ah[mt][1] = *reinterpret_cast<const uint32_t*>(&Ah[(r + 8) * GST + kb]);
                ah[mt][2] = *reinterpret_cast<const uint32_t*>(&Ah[r * GST + kb + 8]);
                ah[mt][3] = *reinterpret_cast<const uint32_t*>(&Ah[(r + 8) * GST + kb + 8]);
            }
#pragma unroll
            for (int nt = 0; nt < 8; nt++) {
                const int n = wn + nt * 8 + lr;
                uint32_t bhv[2], blv[2];
                bhv[0] = *reinterpret_cast<const uint32_t*>(&Bh[n * GST + kb]);
                bhv[1] = *reinterpret_cast<const uint32_t*>(&Bh[n * GST + kb + 8]);
                blv[0] = *reinterpret_cast<const uint32_t*>(&Bl[n * GST + kb]);
                blv[1] = *reinterpret_cast<const uint32_t*>(&Bl[n * GST + kb + 8]);
#pragma unroll
                for (int mt = 0; mt < 2; mt++) {
                    mma_f16(cfr[mt][nt], ah[mt], bhv);
                    mma_f16(cfr[mt][nt], ah[mt], blv);
                }
            }
        }

        if (!more) break;
        __syncthreads();
    }

#pragma unroll
    for (int mt = 0; mt < 2; mt++)
#pragma unroll
        for (int nt = 0; nt < 8; nt++) {
            const int row = bm0 + wm + mt * 16 + lr;
            const int col = bn0 + wn + nt * 8 + lc * 2;
            *reinterpret_cast<float2*>(&C[(size_t)row * Ndim + col]) =
                make_float2(cfr[mt][nt][0], cfr[mt][nt][1]);
            *reinterpret_cast<float2*>(&C[(size_t)(row + 8) * Ndim + col]) =
                make_float2(cfr[mt][nt][2], cfr[mt][nt][3]);
        }
}

// ---------------------------------------------------------------------------
// Flash attention fp16-3term, RoPE fused into Q/K tile loads. (R7-proven.)
// Per block: one (b,h), 64 q rows, 256 threads = 8 warps, 2 CTAs/SM.
// ---------------------------------------------------------------------------
constexpr int FBQ = 64;
constexpr int FBK = 64;
constexpr int H_ST  = 136;   // halves stride (128 data + 8 pad)
constexpr int SS_ST = 68;    // f32 scores stride
constexpr int FLASH_SMEM_BYTES =
    5 * (64 * H_ST * 2) + (FBQ * SS_ST + 3 * FBQ) * 4;   // 105216

__global__ __launch_bounds__(256, 2)
void flash_kernel(const float* __restrict__ Qf, const float* __restrict__ Kf,
                  const float* __restrict__ Vf, float* __restrict__ Of,
                  const float* __restrict__ cosv, const float* __restrict__ sinv)
{
    extern __shared__ char smraw[];
    __half* Qh = reinterpret_cast<__half*>(smraw);            // [64][136]
    __half* Ql = Qh + 64 * H_ST;
    __half* Kh = Ql + 64 * H_ST;
    __half* Kl = Kh + 64 * H_ST;
    __half* Vh = Kl + 64 * H_ST;                               // [kv][d]
    float*  Ss = reinterpret_cast<float*>(Vh + 64 * H_ST);     // [64][68]
    float* m_sm = Ss + FBQ * SS_ST;
    float* l_sm = m_sm + FBQ;
    float* a_sm = l_sm + FBQ;

    const int tid = threadIdx.x;
    const int lane = tid & 31;
    const int wid = tid >> 5;
    const int lr = lane >> 2;
    const int lc = lane & 3;

    const int qt = blockIdx.x;
    const int bh = blockIdx.y;
    const int b = bh / NHEADS;
    const int h = bh - b * NHEADS;
    const int hk = h / GRP;

    const float SCALE = 0.0883883476483184f;   // 1/sqrt(128), applied post-mma

    const int wmS = (wid >> 1) * 16;
    const int wnS = (wid & 1) * 32;
    const int wmP = wmS;
    const int wnP = (wid & 1) * 64;

    // ---- load Q tile with fused RoPE, split hi/lo ----
    {
        const size_t qbase = ((size_t)(b * SEQ + qt * FBQ)) * NQCOLS + h * HDIM;
#pragma unroll
        for (int it = 0; it < 8; it++) {
            const int f = tid + it * 256;
            const int r = f >> 5;
            const int d = (f & 31) * 4;
            const int t = qt * FBQ + r;
            float4 v = *reinterpret_cast<const float4*>(&Qf[qbase + (size_t)r * NQCOLS + d]);
            const float c0 = cosv[t * 64 + d / 2],     s0 = sinv[t * 64 + d / 2];
            const float c1 = cosv[t * 64 + d / 2 + 1], s1 = sinv[t * 64 + d / 2 + 1];
            float x0 = v.x * c0 - v.y * s0, x1 = v.x * s0 + v.y * c0;
            float x2 = v.z * c1 - v.w * s1, x3 = v.z * s1 + v.w * c1;
            uint32_t h0, l0, h1, l1;
            split_pair(x0, x1, h0, l0);
            split_pair(x2, x3, h1, l1);
            *reinterpret_cast<uint2*>(&Qh[r * H_ST + d]) = make_uint2(h0, h1);
            *reinterpret_cast<uint2*>(&Ql[r * H_ST + d]) = make_uint2(l0, l1);
        }
    }
    if (tid < FBQ) { m_sm[tid] = -1e30f; l_sm[tid] = 0.f; }

    float acc[8][4];
#pragma unroll
    for (int nt = 0; nt < 8; nt++)
#pragma unroll
        for (int q = 0; q < 4; q++) acc[nt][q] = 0.f;

    for (int kt = 0; kt <= qt; kt++) {
        __syncthreads();

        // ---- load K (roped, hi/lo) and V (hi) tiles ----
        {
            const size_t kvbase = ((size_t)(b * SEQ + kt * FBK)) * NKVCOLS + hk * HDIM;
#pragma unroll
            for (int it = 0; it < 8; it++) {
                const int f = tid + it * 256;
                const int r = f >> 5;
                const int d = (f & 31) * 4;
                const int t = kt * FBK + r;
                float4 kv = *reinterpret_cast<const float4*>(&Kf[kvbase + (size_t)r * NKVCOLS + d]);
                const float c0 = cosv[t * 64 + d / 2],     s0 = sinv[t * 64 + d / 2];
                const float c1 = cosv[t * 64 + d / 2 + 1], s1 = sinv[t * 64 + d / 2 + 1];
                float x0 = kv.x * c0 - kv.y * s0, x1 = kv.x * s0 + kv.y * c0;
                float x2 = kv.z * c1 - kv.w * s1, x3 = kv.z * s1 + kv.w * c1;
                uint32_t h0, l0, h1, l1;
                split_pair(x0, x1, h0, l0);
                split_pair(x2, x3, h1, l1);
                *reinterpret_cast<uint2*>(&Kh[r * H_ST + d]) = make_uint2(h0, h1);
                *reinterpret_cast<uint2*>(&Kl[r * H_ST + d]) = make_uint2(l0, l1);
                float4 vv = *reinterpret_cast<const float4*>(&Vf[kvbase + (size_t)r * NKVCOLS + d]);
                __half2 vh0 = __float22half2_rn(make_float2(vv.x, vv.y));
                __half2 vh1 = __float22half2_rn(make_float2(vv.z, vv.w));
                *reinterpret_cast<uint2*>(&Vh[r * H_ST + d]) =
                    make_uint2(*reinterpret_cast<uint32_t*>(&vh0), *reinterpret_cast<uint32_t*>(&vh1));
            }
        }
        __syncthreads();

        // ---- scores: S = Q K^T, fp16 3-term ----
        {
            float cs[4][4];
#pragma unroll
            for (int nt = 0; nt < 4; nt++)
#pragma unroll
                for (int q = 0; q < 4; q++) cs[nt][q] = 0.f;

#pragma unroll
            for (int ks = 0; ks < HDIM / 16; ks++) {
                const int kb = ks * 16 + 2 * lc;
                uint32_t qh[4], ql[4];
                qh[0] = *reinterpret_cast<const uint32_t*>(&Qh[(wmS + lr) * H_ST + kb]);
                qh[1] = *reinterpret_cast<const uint32_t*>(&Qh[(wmS + lr + 8) * H_ST + kb]);
                qh[2] = *reinterpret_cast<const uint32_t*>(&Qh[(wmS + lr) * H_ST + kb + 8]);
                qh[3] = *reinterpret_cast<const uint32_t*>(&Qh[(wmS + lr + 8) * H_ST + kb + 8]);
                ql[0] = *reinterpret_cast<const uint32_t*>(&Ql[(wmS + lr) * H_ST + kb]);
                ql[1] = *reinterpret_cast<const uint32_t*>(&Ql[(wmS + lr + 8) * H_ST + kb]);
                ql[2] = *reinterpret_cast<const uint32_t*>(&Ql[(wmS + lr) * H_ST + kb + 8]);
                ql[3] = *reinterpret_cast<const uint32_t*>(&Ql[(wmS + lr + 8) * H_ST + kb + 8]);
#pragma unroll
                for (int nt = 0; nt < 4; nt++) {
                    const int n = wnS + nt * 8 + lr;
                    uint32_t kh[2], kl[2];
                    kh[0] = *reinterpret_cast<const uint32_t*>(&Kh[n * H_ST + kb]);
                    kh[1] = *reinterpret_cast<const uint32_t*>(&Kh[n * H_ST + kb + 8]);
                    kl[0] = *reinterpret_cast<const uint32_t*>(&Kl[n * H_ST + kb]);
                    kl[1] = *reinterpret_cast<const uint32_t*>(&Kl[n * H_ST + kb + 8]);
                    mma_f16(cs[nt], qh, kh);
                    mma_f16(cs[nt], qh, kl);
                    mma_f16(cs[nt], ql, kh);
                }
            }

            if (kt == qt) {
                const int grow0 = qt * FBQ + wmS + lr;
                const int gcolb = kt * FBK + wnS;
#pragma unroll
                for (int nt = 0; nt < 4; nt++) {
                    const int c = wnS + nt * 8 + lc * 2;
                    const int gc = gcolb + nt * 8 + lc * 2;
                    float v0 = (gc     > grow0) ? -1e30f : cs[nt][0] * SCALE;
                    float v1 = (gc + 1 > grow0) ? -1e30f : cs[nt][1] * SCALE;
                    float v2 = (gc     > grow0 + 8) ? -1e30f : cs[nt][2] * SCALE;
                    float v3 = (gc + 1 > grow0 + 8) ? -1e30f : cs[nt][3] * SCALE;
                    *reinterpret_cast<float2*>(&Ss[(wmS + lr) * SS_ST + c])     = make_float2(v0, v1);
                    *reinterpret_cast<float2*>(&Ss[(wmS + lr + 8) * SS_ST + c]) = make_float2(v2, v3);
                }
            } else {
#pragma unroll
                for (int nt = 0; nt < 4; nt++) {
                    const int c = wnS + nt * 8 + lc * 2;
                    *reinterpret_cast<float2*>(&Ss[(wmS + lr) * SS_ST + c]) =
                        make_float2(cs[nt][0] * SCALE, cs[nt][1] * SCALE);
                    *reinterpret_cast<float2*>(&Ss[(wmS + lr + 8) * SS_ST + c]) =
                        make_float2(cs[nt][2] * SCALE, cs[nt][3] * SCALE);
                }
            }
        }
        __syncthreads();

        // ---- online softmax ----
        {
            const int row = tid >> 2;
            const int g = tid & 3;
            float* Sr = &Ss[row * SS_ST + g * 16];
            float mloc = -1e30f;
#pragma unroll
            for (int jj = 0; jj < 16; jj++) mloc = fmaxf(mloc, Sr[jj]);
            mloc = fmaxf(mloc, __shfl_xor_sync(0xffffffffu, mloc, 1));
            mloc = fmaxf(mloc, __shfl_xor_sync(0xffffffffu, mloc, 2));
            const float mold = m_sm[row];
            const float mnew = fmaxf(mold, mloc);
            const float alpha = __expf(mold - mnew);
            float ssum = 0.f;
#pragma unroll
            for (int jj = 0; jj < 16; jj++) {
                float p = __expf(Sr[jj] - mnew);
                Sr[jj] = p;
                ssum += p;
            }
            ssum += __shfl_xor_sync(0xffffffffu, ssum, 1);
            ssum += __shfl_xor_sync(0xffffffffu, ssum, 2);
            if (g == 0) {
                m_sm[row] = mnew;
                l_sm[row] = l_sm[row] * alpha + ssum;
                a_sm[row] = alpha;
            }
        }
        __syncthreads();

        // ---- PV: O += P V  (P exact hi+lo; V hi-only) ----
        {
            const float al0 = a_sm[wmP + lr];
            const float al1 = a_sm[wmP + lr + 8];
#pragma unroll
            for (int nt = 0; nt < 8; nt++) {
                acc[nt][0] *= al0; acc[nt][1] *= al0;
                acc[nt][2] *= al1; acc[nt][3] *= al1;
            }

#pragma unroll
            for (int ks = 0; ks < FBK / 16; ks++) {
                const int kb = ks * 16 + 2 * lc;
                float2 p00 = *reinterpret_cast<const float2*>(&Ss[(wmP + lr) * SS_ST + kb]);
                float2 p01 = *reinterpret_cast<const float2*>(&Ss[(wmP + lr + 8) * SS_ST + kb]);
                float2 p10 = *reinterpret_cast<const float2*>(&Ss[(wmP + lr) * SS_ST + kb + 8]);
                float2 p11 = *reinterpret_cast<const float2*>(&Ss[(wmP + lr + 8) * SS_ST + kb + 8]);
                uint32_t ph[4], pl[4];
                split_pair(p00.x, p00.y, ph[0], pl[0]);
                split_pair(p01.x, p01.y, ph[1], pl[1]);
                split_pair(p10.x, p10.y, ph[2], pl[2]);
                split_pair(p11.x, p11.y, ph[3], pl[3]);
#pragma unroll
                for (int nt = 0; nt < 8; nt++) {
                    const int n = wnP + nt * 8 + lr;
                    __half2 b0 = __halves2half2(Vh[(kb + 0) * H_ST + n], Vh[(kb + 1) * H_ST + n]);
                    __half2 b1 = __halves2half2(Vh[(kb + 8) * H_ST + n], Vh[(kb + 9) * H_ST + n]);
                    uint32_t vb[2] = {*reinterpret_cast<uint32_t*>(&b0),
                                      *reinterpret_cast<uint32_t*>(&b1)};
                    mma_f16(acc[nt], ph, vb);
                    mma_f16(acc[nt], pl, vb);
                }
            }
        }
    }

    // epilogue
    __syncthreads();
    {
        const float inv0 = 1.0f / l_sm[wmP + lr];
        const float inv1 = 1.0f / l_sm[wmP + lr + 8];
        const size_t ob0 = ((size_t)(b * SEQ + qt * FBQ + wmP + lr)) * NQCOLS + h * HDIM;
        const size_t ob1 = ((size_t)(b * SEQ + qt * FBQ + wmP + lr + 8)) * NQCOLS + h * HDIM;
#pragma unroll
        for (int nt = 0; nt < 8; nt++) {
            const int c = wnP + nt * 8 + lc * 2;
            *reinterpret_cast<float2*>(&Of[ob0 + c]) =
                make_float2(acc[nt][0] * inv0, acc[nt][1] * inv0);
            *reinterpret_cast<float2*>(&Of[ob1 + c]) =
                make_float2(acc[nt][2] * inv1, acc[nt][3] * inv1);
        }
    }
}

// ---------------------------------------------------------------------------
// Launch
// ---------------------------------------------------------------------------
extern "C" void kernel_launch(void* const* d_in, const int* in_sizes, int n_in,
                              void* d_out, int out_size)
{
    (void)in_sizes; (void)n_in; (void)out_size;
    const float* X        = (const float*)d_in[0];
    const float* cosv     = (const float*)d_in[1];
    const float* sinv     = (const float*)d_in[2];
    // d_in[3] = position_ids (arange(S) broadcast; computed analytically)
    // d_in[4] = attention_mask (causal; applied analytically)
    const float* Wq       = (const float*)d_in[5];
    const float* Wk       = (const float*)d_in[6];
    const float* Wv       = (const float*)d_in[7];
    const float* Wo       = (const float*)d_in[8];
    float* out            = (float*)d_out;

    float *qp, *kp, *vp, *aop;
    cudaGetSymbolAddress((void**)&qp,  g_Q);
    cudaGetSymbolAddress((void**)&kp,  g_K);
    cudaGetSymbolAddress((void**)&vp,  g_V);
    cudaGetSymbolAddress((void**)&aop, g_AO);

    // QKV projections (fp16 2-term tensor cores)
    hgemm_nt_2t<<<dim3(NQCOLS / TBN, MROWS / TBM), 256>>>(X, Wq, qp, NQCOLS, HID);
    hgemm_nt_2t<<<dim3(NKVCOLS / TBN, MROWS / TBM), 256>>>(X, Wk, kp, NKVCOLS, HID);
    hgemm_nt_2t<<<dim3(NKVCOLS / TBN, MROWS / TBM), 256>>>(X, Wv, vp, NKVCOLS, HID);

    // Flash attention (RoPE fused into Q/K loads)
    cudaFuncSetAttribute(flash_kernel, cudaFuncAttributeMaxDynamicSharedMemorySize,
                         FLASH_SMEM_BYTES);
    flash_kernel<<<dim3(SEQ / FBQ, BATCH * NHEADS), 256, FLASH_SMEM_BYTES>>>(
        qp, kp, vp, aop, cosv, sinv);

    // Output projection -> d_out
    hgemm_nt_2t<<<dim3(HID / TBN, MROWS / TBM), 256>>>(aop, Wo, out, HID, NQCOLS);
}